// round 4
// baseline (speedup 1.0000x reference)
#include <cuda_runtime.h>
#include <cstdint>

typedef unsigned long long ull;

#define TPB   512
#define NB    8
#define R_    16
#define D_    1024

// ---- packed f32x2 helpers (Blackwell sm_103a) ----
__device__ __forceinline__ ull ffma2(ull a, ull b, ull c) {
    ull d;
    asm("fma.rn.f32x2 %0, %1, %2, %3;" : "=l"(d) : "l"(a), "l"(b), "l"(c));
    return d;
}
__device__ __forceinline__ ull fmul2(ull a, ull b) {
    ull d;
    asm("mul.rn.f32x2 %0, %1, %2;" : "=l"(d) : "l"(a), "l"(b));
    return d;
}
__device__ __forceinline__ ull fadd2(ull a, ull b) {
    ull d;
    asm("add.rn.f32x2 %0, %1, %2;" : "=l"(d) : "l"(a), "l"(b));
    return d;
}
__device__ __forceinline__ float lo_(ull v) { return __int_as_float((int)(unsigned)(v & 0xffffffffull)); }
__device__ __forceinline__ float hi_(ull v) { return __int_as_float((int)(unsigned)(v >> 32)); }
__device__ __forceinline__ ull   dup_(float v) { unsigned u = __float_as_uint(v); return ((ull)u << 32) | (ull)u; }
__device__ __forceinline__ ull   pack2_(float l, float h) {
    unsigned ul = __float_as_uint(l), uh = __float_as_uint(h);
    return ((ull)uh << 32) | (ull)ul;
}
__device__ __forceinline__ unsigned sptr(const void* p) {
    return (unsigned)__cvta_generic_to_shared(p);
}
__device__ __forceinline__ void cpa8(unsigned dst, const void* src) {
    asm volatile("cp.async.ca.shared.global [%0], [%1], 8;" :: "r"(dst), "l"(src));
}

// ---- dynamic smem layout ----
#define XBUF_OFF 0                      // ull [4][NB][TPB]      131072 B
#define RED2_OFF 131072                 // ull [2][NB][TPB/2]     32768 B
#define RED1_OFF 163840                 // float [2][NB][TPB/4]    8192 B
#define SB_OFF   172032                 // ull [2][NB][R_]         2048 B
#define SIDX_OFF 174080                 // int [4][NB]              128 B
#define SCX_OFF  174208                 // ull [2][NB]              128 B
#define SCY_OFF  174336                 // ull [2][NB]              128 B
#define SMEM_TOTAL 174464

__global__ __launch_bounds__(TPB, 1)
void rlora_kernel(const int*   __restrict__ indices,
                  const float* __restrict__ baseW,
                  const float* __restrict__ loraA,
                  const float* __restrict__ loraB,
                  float*       __restrict__ out,
                  int n_rows, int nbatch)
{
    extern __shared__ char smem_raw[];
    ull   (*xbuf)[NB][TPB]     = reinterpret_cast<ull(*)[NB][TPB]>(smem_raw + XBUF_OFF);
    ull   (*red2)[NB][TPB / 2] = reinterpret_cast<ull(*)[NB][TPB / 2]>(smem_raw + RED2_OFF);
    float (*red1)[NB][TPB / 4] = reinterpret_cast<float(*)[NB][TPB / 4]>(smem_raw + RED1_OFF);
    ull   (*sb)[NB][R_]        = reinterpret_cast<ull(*)[NB][R_]>(smem_raw + SB_OFF);
    int   (*sidx)[NB]          = reinterpret_cast<int(*)[NB]>(smem_raw + SIDX_OFF);
    ull   (*scx)[NB]           = reinterpret_cast<ull(*)[NB]>(smem_raw + SCX_OFF);
    ull   (*scy)[NB]           = reinterpret_cast<ull(*)[NB]>(smem_raw + SCY_OFF);

    const int tid  = threadIdx.x;
    const int wid  = tid >> 5;
    const int lane = tid & 31;
    const int d0   = tid * 2;

    // lora_A register-resident (32 regs)
    ull a[R_];
    #pragma unroll
    for (int r = 0; r < R_; ++r)
        a[r] = __ldg(reinterpret_cast<const ull*>(loraA + r * D_ + d0));

    const int S    = gridDim.x;
    const int b0   = blockIdx.x;
    const int kmax = (nbatch - b0 + S - 1) / S;   // batches for this block (>=1)

    // ---------------- prologue ----------------
    // cp.async groups for batches 0 and 1
    #pragma unroll
    for (int m = 0; m < 2; ++m) {
        if (m < kmax) {
            #pragma unroll
            for (int row = 0; row < NB; ++row) {
                int g = (b0 + m * S) * NB + row;
                if (g < n_rows) {
                    int idx = __ldg(indices + g);
                    cpa8(sptr(&xbuf[m][row][tid]), baseW + (size_t)idx * D_ + d0);
                }
            }
        }
        asm volatile("cp.async.commit_group;");
    }
    // sidx slots 1..3 = indices of batches 1..3
    if (tid < NB) {
        #pragma unroll
        for (int m = 1; m < 4; ++m) {
            int g = (b0 + m * S) * NB + tid;
            sidx[m][tid] = (m < kmax && g < n_rows) ? __ldg(indices + g) : -1;
        }
    }
    // sb for batch 0 (slot 0)
    if (tid < NB * R_) {
        int row = tid >> 4, r = tid & 15;
        int g = b0 * NB + row;
        sb[0][row][r] = (g < n_rows)
            ? dup_(0.1f * __ldg(loraB + (size_t)__ldg(indices + g) * R_ + r)) : 0ull;
    }
    __syncthreads();

    ull dvp[NB];   // delta of previous batch (for deferred store)

    for (int k = 0; k < kmax; ++k) {
        // ---- step 1: cp.async prefetch x(k+2) ----
        {
            const bool ok = (k + 2) < kmax;
            const int  xs = (k + 2) & 3;
            #pragma unroll
            for (int row = 0; row < NB; ++row) {
                int idx = ok ? sidx[(k + 2) & 3][row] : -1;
                if (idx >= 0)
                    cpa8(sptr(&xbuf[xs][row][tid]), baseW + (size_t)idx * D_ + d0);
            }
            asm volatile("cp.async.commit_group;");
        }
        // ---- step 2: stage sidx(k+3), sb(k+1) ----
        if (tid < NB) {
            long long g = (long long)(b0 + (k + 3) * S) * NB + tid;
            sidx[(k + 3) & 3][tid] = ((k + 3) < kmax && g < n_rows)
                                     ? __ldg(indices + g) : -1;
        }
        if (tid < NB * R_) {
            int row = tid >> 4, r = tid & 15;
            int idx = ((k + 1) < kmax) ? sidx[(k + 1) & 3][row] : -1;
            sb[(k + 1) & 1][row][r] = (idx >= 0)
                ? dup_(0.1f * __ldg(loraB + (size_t)idx * R_ + r)) : 0ull;
        }

        // ---- step 3: ensure x(k) arrived (keep 2 newer groups pending) ----
        asm volatile("cp.async.wait_group 2;" ::: "memory");

        // ---- step 4: compute delta(k) + prefolded partials -> red[k&1] ----
        const int p = k & 1;
        ull dvc[NB];
        #pragma unroll
        for (int row = 0; row < NB; ++row) {
            ull xv = xbuf[k & 3][row][tid];
            const ulonglong2* bp = reinterpret_cast<const ulonglong2*>(sb[p][row]);
            ulonglong2 b01 = bp[0];
            ull acc0 = fmul2(b01.x, a[0]);
            ull acc1 = fmul2(b01.y, a[1]);
            #pragma unroll
            for (int kk = 1; kk < R_ / 2; ++kk) {
                ulonglong2 b = bp[kk];
                acc0 = ffma2(b.x, a[2 * kk],     acc0);
                acc1 = ffma2(b.y, a[2 * kk + 1], acc1);
            }
            ull dv = fadd2(acc0, acc1);
            dvc[row] = dv;

            float xl = lo_(xv), xh = hi_(xv);
            float yl = lo_(dv), yh = hi_(dv);
            float x2p = fmaf(xl, xl, xh * xh);
            float xyp = fmaf(xl, yl, xh * yh);
            float y2p = fmaf(yl, yl, yh * yh);
            x2p += __shfl_xor_sync(0xffffffffu, x2p, 16);
            xyp += __shfl_xor_sync(0xffffffffu, xyp, 16);
            y2p += __shfl_xor_sync(0xffffffffu, y2p, 16);
            y2p += __shfl_xor_sync(0xffffffffu, y2p, 8);
            if (lane < 16) red2[p][row][wid * 16 + lane] = pack2_(x2p, xyp);
            if (lane < 8)  red1[p][row][wid * 8 + lane]  = y2p;
        }

        // ---- step 5: reduce batch k-1 (concurrent with step 4 issue-wise) ----
        if (k >= 1 && wid < NB) {
            const int pp = (k - 1) & 1;
            const ulonglong2* p2 = reinterpret_cast<const ulonglong2*>(red2[pp][wid]);
            ulonglong2 v0 = p2[lane], v1 = p2[lane + 32], v2 = p2[lane + 64], v3 = p2[lane + 96];
            ull sp = fadd2(fadd2(fadd2(v0.x, v0.y), fadd2(v1.x, v1.y)),
                           fadd2(fadd2(v2.x, v2.y), fadd2(v3.x, v3.y)));
            const float* r1 = red1[pp][wid];
            float s2 = (r1[lane] + r1[lane + 32]) + (r1[lane + 64] + r1[lane + 96]);

            float a0 = lo_(sp), a1 = hi_(sp);
            #pragma unroll
            for (int off = 16; off > 0; off >>= 1) {
                a0 += __shfl_xor_sync(0xffffffffu, a0, off);
                a1 += __shfl_xor_sync(0xffffffffu, a1, off);
                s2 += __shfl_xor_sync(0xffffffffu, s2, off);
            }
            if (lane == 0) {
                const float MAXN = 1.0f - 1e-5f;
                const float EPSN = 1e-5f;
                float x2 = a0, xy = a1, y2 = s2;

                float nx = sqrtf(x2);
                float sx = (nx > MAXN) ? __fdividef(MAXN, fmaxf(nx, EPSN)) : 1.0f;
                float ny = sqrtf(y2);
                float sy = (ny > MAXN) ? __fdividef(MAXN, fmaxf(ny, EPSN)) : 1.0f;

                float X2 = sx * sx * x2;
                float Y2 = sy * sy * y2;
                float XY = sx * sy * xy;

                float A_  = 1.0f + 2.0f * XY + Y2;
                float B_  = 1.0f - X2;
                float den = fmaxf(1.0f + 2.0f * XY + X2 * Y2, 1e-15f);

                float n2 = (A_ * A_ * X2 + 2.0f * A_ * B_ * XY + B_ * B_ * Y2)
                           / (den * den);
                float no = sqrtf(fmaxf(n2, 0.0f));
                float sf = (no > MAXN) ? __fdividef(MAXN, fmaxf(no, EPSN)) : 1.0f;

                scx[pp][wid] = dup_(__fdividef(sf * A_ * sx, den));
                scy[pp][wid] = dup_(__fdividef(sf * B_ * sy, den));
            }
        }
        __syncthreads();

        // ---- step 7: store batch k-1 ----
        if (k >= 1) {
            const int pp  = (k - 1) & 1;
            const int xs  = (k - 1) & 3;
            const long long row0 = (long long)(b0 + (k - 1) * S) * NB;
            #pragma unroll
            for (int row = 0; row < NB; ++row) {
                long long g = row0 + row;
                if (g < n_rows) {
                    ull xp = xbuf[xs][row][tid];
                    ull o  = ffma2(scx[pp][row], xp, fmul2(scy[pp][row], dvp[row]));
                    __stcs(reinterpret_cast<ull*>(out + (size_t)g * D_ + d0), o);
                }
            }
        }
        #pragma unroll
        for (int row = 0; row < NB; ++row) dvp[row] = dvc[row];
        __syncthreads();
    }

    // ---------------- tail: reduce + store last batch ----------------
    {
        const int kl = kmax - 1;
        if (wid < NB) {
            const int pp = kl & 1;
            const ulonglong2* p2 = reinterpret_cast<const ulonglong2*>(red2[pp][wid]);
            ulonglong2 v0 = p2[lane], v1 = p2[lane + 32], v2 = p2[lane + 64], v3 = p2[lane + 96];
            ull sp = fadd2(fadd2(fadd2(v0.x, v0.y), fadd2(v1.x, v1.y)),
                           fadd2(fadd2(v2.x, v2.y), fadd2(v3.x, v3.y)));
            const float* r1 = red1[pp][wid];
            float s2 = (r1[lane] + r1[lane + 32]) + (r1[lane + 64] + r1[lane + 96]);

            float a0 = lo_(sp), a1 = hi_(sp);
            #pragma unroll
            for (int off = 16; off > 0; off >>= 1) {
                a0 += __shfl_xor_sync(0xffffffffu, a0, off);
                a1 += __shfl_xor_sync(0xffffffffu, a1, off);
                s2 += __shfl_xor_sync(0xffffffffu, s2, off);
            }
            if (lane == 0) {
                const float MAXN = 1.0f - 1e-5f;
                const float EPSN = 1e-5f;
                float x2 = a0, xy = a1, y2 = s2;
                float nx = sqrtf(x2);
                float sx = (nx > MAXN) ? __fdividef(MAXN, fmaxf(nx, EPSN)) : 1.0f;
                float ny = sqrtf(y2);
                float sy = (ny > MAXN) ? __fdividef(MAXN, fmaxf(ny, EPSN)) : 1.0f;
                float X2 = sx * sx * x2;
                float Y2 = sy * sy * y2;
                float XY = sx * sy * xy;
                float A_  = 1.0f + 2.0f * XY + Y2;
                float B_  = 1.0f - X2;
                float den = fmaxf(1.0f + 2.0f * XY + X2 * Y2, 1e-15f);
                float n2 = (A_ * A_ * X2 + 2.0f * A_ * B_ * XY + B_ * B_ * Y2)
                           / (den * den);
                float no = sqrtf(fmaxf(n2, 0.0f));
                float sf = (no > MAXN) ? __fdividef(MAXN, fmaxf(no, EPSN)) : 1.0f;
                scx[pp][wid] = dup_(__fdividef(sf * A_ * sx, den));
                scy[pp][wid] = dup_(__fdividef(sf * B_ * sy, den));
            }
        }
        __syncthreads();
        const int pp = kl & 1;
        const int xs = kl & 3;
        const long long row0 = (long long)(b0 + kl * S) * NB;
        #pragma unroll
        for (int row = 0; row < NB; ++row) {
            long long g = row0 + row;
            if (g < n_rows) {
                ull xp = xbuf[xs][row][tid];
                ull o  = ffma2(scx[pp][row], xp, fmul2(scy[pp][row], dvp[row]));
                __stcs(reinterpret_cast<ull*>(out + (size_t)g * D_ + d0), o);
            }
        }
    }
}

extern "C" void kernel_launch(void* const* d_in, const int* in_sizes, int n_in,
                              void* d_out, int out_size)
{
    const int*   indices = (const int*)  d_in[0];
    const float* baseW   = (const float*)d_in[1];
    const float* loraA   = (const float*)d_in[2];
    const float* loraB   = (const float*)d_in[3];
    float*       out     = (float*)d_out;

    int n_rows = in_sizes[0];                    // 32768
    int nbatch = (n_rows + NB - 1) / NB;         // 4096
    int grid   = nbatch < 148 ? nbatch : 148;

    cudaFuncSetAttribute(rlora_kernel,
                         cudaFuncAttributeMaxDynamicSharedMemorySize, SMEM_TOTAL);
    rlora_kernel<<<grid, TPB, SMEM_TOTAL>>>(indices, baseW, loraA, loraB, out,
                                            n_rows, nbatch);
}

// round 5
// speedup vs baseline: 1.1630x; 1.1630x over previous
#include <cuda_runtime.h>
#include <cstdint>

typedef unsigned long long ull;

#define TPB   256
#define NB    4
#define R_    16
#define D_    1024

// ---- packed f32x2 helpers ----
__device__ __forceinline__ ull ffma2(ull a, ull b, ull c) {
    ull d;
    asm("fma.rn.f32x2 %0, %1, %2, %3;" : "=l"(d) : "l"(a), "l"(b), "l"(c));
    return d;
}
__device__ __forceinline__ ull fmul2(ull a, ull b) {
    ull d;
    asm("mul.rn.f32x2 %0, %1, %2;" : "=l"(d) : "l"(a), "l"(b));
    return d;
}
__device__ __forceinline__ ull fadd2(ull a, ull b) {
    ull d;
    asm("add.rn.f32x2 %0, %1, %2;" : "=l"(d) : "l"(a), "l"(b));
    return d;
}
__device__ __forceinline__ float lo_(ull v) { return __int_as_float((int)(unsigned)(v & 0xffffffffull)); }
__device__ __forceinline__ float hi_(ull v) { return __int_as_float((int)(unsigned)(v >> 32)); }
__device__ __forceinline__ ull   dup_(float v) { unsigned u = __float_as_uint(v); return ((ull)u << 32) | (ull)u; }
__device__ __forceinline__ ull   pack2_(float l, float h) {
    unsigned ul = __float_as_uint(l), uh = __float_as_uint(h);
    return ((ull)uh << 32) | (ull)ul;
}
__device__ __forceinline__ ulonglong2 ldg128(const void* p) {
    ulonglong2 v;
    asm("ld.global.nc.v2.u64 {%0, %1}, [%2];" : "=l"(v.x), "=l"(v.y) : "l"(p));
    return v;
}
__device__ __forceinline__ void stcs128(void* p, ull a, ull b) {
    asm volatile("st.global.cs.v2.u64 [%0], {%1, %2};" :: "l"(p), "l"(a), "l"(b));
}

__global__ __launch_bounds__(TPB, 2)
void rlora_kernel(const int*   __restrict__ indices,
                  const float* __restrict__ baseW,
                  const float* __restrict__ loraA,
                  const float* __restrict__ loraB,
                  float*       __restrict__ out,
                  int n_rows, int nbatch)
{
    // per-CTA static smem (~6.2 KB) — 2 CTAs/SM co-resident
    __shared__ ull   red2[NB][TPB / 2];   // packed (x2,xy), prefolded by 16
    __shared__ float red1[NB][TPB / 4];   // y2, prefolded by 16+8
    __shared__ ull   sb[2][NB][R_];       // 0.1*loraB rows, dup'd
    __shared__ int   sidx[2][NB];
    __shared__ ull   scx[NB], scy[NB];

    const int tid  = threadIdx.x;
    const int wid  = tid >> 5;
    const int lane = tid & 31;
    const int d0   = tid * 4;             // this lane owns columns d0..d0+3

    // lora_A register-resident: a2[r] = A[r][d0..d0+3] (64 regs)
    ulonglong2 a2[R_];
    #pragma unroll
    for (int r = 0; r < R_; ++r)
        a2[r] = ldg128(loraA + r * D_ + d0);

    const int S    = gridDim.x;
    const int b0   = blockIdx.x;
    const int kmax = (nbatch - b0 + S - 1) / S;

    // ---------------- prologue ----------------
    ulonglong2 xc[NB];
    {
        #pragma unroll
        for (int row = 0; row < NB; ++row) {
            int g = b0 * NB + row;
            if (g < n_rows) {
                int idx = __ldg(indices + g);
                xc[row] = ldg128(baseW + (size_t)idx * D_ + d0);
            } else xc[row] = make_ulonglong2(0ull, 0ull);
        }
        if (tid < NB) {
            int g = (b0 + S) * NB + tid;
            sidx[1][tid] = ((b0 + S) < nbatch && g < n_rows) ? __ldg(indices + g) : -1;
        }
        if (tid < NB * R_) {
            int row = tid >> 4, r = tid & 15;
            int g = b0 * NB + row;
            sb[0][row][r] = (g < n_rows)
                ? dup_(0.1f * __ldg(loraB + (size_t)__ldg(indices + g) * R_ + r)) : 0ull;
        }
    }
    __syncthreads();

    for (int k = 0; k < kmax; ++k) {
        const int B        = b0 + k * S;
        const bool havenext = (k + 1) < kmax;
        const int p        = k & 1;

        // ---- prefetch x(k+1) into registers ----
        ulonglong2 xn[NB];
        #pragma unroll
        for (int row = 0; row < NB; ++row) {
            int idx = havenext ? sidx[(k + 1) & 1][row] : -1;
            xn[row] = (idx >= 0) ? ldg128(baseW + (size_t)idx * D_ + d0)
                                 : make_ulonglong2(0ull, 0ull);
        }
        // ---- stage sidx(k+2) into slot k&1, sb(k+1) into slot (k+1)&1 ----
        if (tid < NB) {
            long long g = (long long)(b0 + (k + 2) * S) * NB + tid;
            sidx[p][tid] = ((k + 2) < kmax && g < n_rows) ? __ldg(indices + g) : -1;
        }
        if (tid < NB * R_) {
            int row = tid >> 4, r = tid & 15;
            int idx = havenext ? sidx[(k + 1) & 1][row] : -1;
            sb[(k + 1) & 1][row][r] = (idx >= 0)
                ? dup_(0.1f * __ldg(loraB + (size_t)idx * R_ + r)) : 0ull;
        }

        // ---- delta + prefolded partials for batch k ----
        ulonglong2 dv[NB];
        #pragma unroll
        for (int row = 0; row < NB; ++row) {
            const ulonglong2* bp = reinterpret_cast<const ulonglong2*>(sb[p][row]);
            ulonglong2 b01 = bp[0];
            ull ax0 = fmul2(b01.x, a2[0].x), ay0 = fmul2(b01.x, a2[0].y);
            ull ax1 = fmul2(b01.y, a2[1].x), ay1 = fmul2(b01.y, a2[1].y);
            #pragma unroll
            for (int kk = 1; kk < R_ / 2; ++kk) {
                ulonglong2 b = bp[kk];
                ax0 = ffma2(b.x, a2[2 * kk].x,     ax0);
                ay0 = ffma2(b.x, a2[2 * kk].y,     ay0);
                ax1 = ffma2(b.y, a2[2 * kk + 1].x, ax1);
                ay1 = ffma2(b.y, a2[2 * kk + 1].y, ay1);
            }
            dv[row].x = fadd2(ax0, ax1);
            dv[row].y = fadd2(ay0, ay1);

            float x0 = lo_(xc[row].x), x1 = hi_(xc[row].x);
            float x2_ = lo_(xc[row].y), x3 = hi_(xc[row].y);
            float y0 = lo_(dv[row].x), y1 = hi_(dv[row].x);
            float y2_ = lo_(dv[row].y), y3 = hi_(dv[row].y);

            float x2p = fmaf(x0, x0, fmaf(x1, x1, fmaf(x2_, x2_, x3 * x3)));
            float xyp = fmaf(x0, y0, fmaf(x1, y1, fmaf(x2_, y2_, x3 * y3)));
            float y2p = fmaf(y0, y0, fmaf(y1, y1, fmaf(y2_, y2_, y3 * y3)));

            x2p += __shfl_xor_sync(0xffffffffu, x2p, 16);
            xyp += __shfl_xor_sync(0xffffffffu, xyp, 16);
            y2p += __shfl_xor_sync(0xffffffffu, y2p, 16);
            y2p += __shfl_xor_sync(0xffffffffu, y2p, 8);
            if (lane < 16) red2[row][wid * 16 + lane] = pack2_(x2p, xyp);
            if (lane < 8)  red1[row][wid * 8 + lane]  = y2p;
        }
        __syncthreads();

        // ---- warp w reduces row w + epilogue ----
        if (wid < NB) {
            const ulonglong2* p2 = reinterpret_cast<const ulonglong2*>(red2[wid]);
            ulonglong2 v0 = p2[lane], v1 = p2[lane + 32];
            ull sp = fadd2(fadd2(v0.x, v0.y), fadd2(v1.x, v1.y));
            const float* r1 = red1[wid];
            float s2 = r1[lane] + r1[lane + 32];

            float a0 = lo_(sp), a1 = hi_(sp);
            #pragma unroll
            for (int off = 16; off > 0; off >>= 1) {
                a0 += __shfl_xor_sync(0xffffffffu, a0, off);
                a1 += __shfl_xor_sync(0xffffffffu, a1, off);
                s2 += __shfl_xor_sync(0xffffffffu, s2, off);
            }
            if (lane == 0) {
                const float MAXN = 1.0f - 1e-5f;
                const float EPSN = 1e-5f;
                float x2 = a0, xy = a1, y2 = s2;

                float nx = sqrtf(x2);
                float sx = (nx > MAXN) ? __fdividef(MAXN, fmaxf(nx, EPSN)) : 1.0f;
                float ny = sqrtf(y2);
                float sy = (ny > MAXN) ? __fdividef(MAXN, fmaxf(ny, EPSN)) : 1.0f;

                float X2 = sx * sx * x2;
                float Y2 = sy * sy * y2;
                float XY = sx * sy * xy;

                float A_  = 1.0f + 2.0f * XY + Y2;
                float B_  = 1.0f - X2;
                float den = fmaxf(1.0f + 2.0f * XY + X2 * Y2, 1e-15f);

                float n2 = (A_ * A_ * X2 + 2.0f * A_ * B_ * XY + B_ * B_ * Y2)
                           / (den * den);
                float no = sqrtf(fmaxf(n2, 0.0f));
                float sf = (no > MAXN) ? __fdividef(MAXN, fmaxf(no, EPSN)) : 1.0f;

                scx[wid] = dup_(__fdividef(sf * A_ * sx, den));
                scy[wid] = dup_(__fdividef(sf * B_ * sy, den));
            }
        }
        __syncthreads();

        // ---- store batch k, rotate prefetch ----
        const long long row0 = (long long)B * NB;
        #pragma unroll
        for (int row = 0; row < NB; ++row) {
            long long g = row0 + row;
            if (g < n_rows) {
                ull o0 = ffma2(scx[row], xc[row].x, fmul2(scy[row], dv[row].x));
                ull o1 = ffma2(scx[row], xc[row].y, fmul2(scy[row], dv[row].y));
                stcs128(out + (size_t)g * D_ + d0, o0, o1);
            }
        }
        #pragma unroll
        for (int row = 0; row < NB; ++row) xc[row] = xn[row];
    }
}

extern "C" void kernel_launch(void* const* d_in, const int* in_sizes, int n_in,
                              void* d_out, int out_size)
{
    const int*   indices = (const int*)  d_in[0];
    const float* baseW   = (const float*)d_in[1];
    const float* loraA   = (const float*)d_in[2];
    const float* loraB   = (const float*)d_in[3];
    float*       out     = (float*)d_out;

    int n_rows = in_sizes[0];                    // 32768
    int nbatch = (n_rows + NB - 1) / NB;         // 8192
    int grid   = nbatch < 2 * 148 ? nbatch : 2 * 148;   // 2 CTAs per SM

    rlora_kernel<<<grid, TPB>>>(indices, baseW, loraA, loraB, out, n_rows, nbatch);
}